// round 14
// baseline (speedup 1.0000x reference)
#include <cuda_runtime.h>
#include <cstdint>
#include <cstddef>

#define LN  1024
#define CC  16
#define NO  64
#define PAD 36      // buf row stride (X staging only): 36 mod 32 = 4, ldmatrix-clean

// ===================== scratch globals ======================================
__device__ float d_Tm[LN*LN*CC];   // masked T, tf32-rounded
__device__ float d_diag[LN*CC];
__device__ float d_cols[LN*CC];
// A-bias in mma fragment order (PERMUTED channels): [strip][warp][m][h][n][lane]
__device__ float2 d_AF2[8*4*2*2*8*32];
__device__ float d_CB[LN*NO];      // permuted channel positions
__device__ float d_diagU[LN*NO];   // TRUE channel order: A + CB(+b1) + D for j==i fixup
// weight fragments, lane-coalesced: flat = ((k*4+q)*32 + lane)*4 + e
// W1F B-columns PERMUTED: position t4 holds channel (t4>>1)+4*(t4&1) within n-tile
__device__ float d_W1F[4*4*32*4];
__device__ float d_W2F[8*4*32*4];  // unpermuted

// ===================== helpers ==============================================
__device__ __forceinline__ float tf32f(float x) {
    uint32_t u;
    asm("cvt.rna.tf32.f32 %0, %1;" : "=r"(u) : "f"(x));
    return __uint_as_float(u);
}
__device__ __forceinline__ void mma8(float c[4], const uint32_t a[4],
                                     uint32_t b0, uint32_t b1) {
    asm volatile(
        "mma.sync.aligned.m16n8k8.row.col.f32.tf32.tf32.f32 "
        "{%0,%1,%2,%3}, {%4,%5,%6,%7}, {%8,%9}, {%0,%1,%2,%3};"
        : "+f"(c[0]), "+f"(c[1]), "+f"(c[2]), "+f"(c[3])
        : "r"(a[0]), "r"(a[1]), "r"(a[2]), "r"(a[3]), "r"(b0), "r"(b1));
}
__device__ __forceinline__ void ldsm4(uint32_t a[4], uint32_t addr) {
    asm volatile("ldmatrix.sync.aligned.m8n8.x4.shared.b16 {%0,%1,%2,%3}, [%4];"
                 : "=r"(a[0]), "=r"(a[1]), "=r"(a[2]), "=r"(a[3]) : "r"(addr));
}
__device__ __forceinline__ uint32_t smem_u32(const void* p) {
    return (uint32_t)__cvta_generic_to_shared(p);
}
__device__ __forceinline__ bool mask_at(const void* M, size_t idx, int mdt)
{
    if (mdt == 0) return ((const unsigned char*)M)[idx] != 0;
    if (mdt == 1) return ((const int*)M)[idx] != 0;
    return ((const float*)M)[idx] != 0.f;
}
__device__ __forceinline__ int detect_mdt(const unsigned char* __restrict__ M,
                                          int t, int* sh2)
{
    if (t == 0) { sh2[0] = 0; sh2[1] = 0; }
    __syncthreads();
    int f32 = 0, u8 = 0;
    for (int w = t; w < 1024; w += 256) {
        unsigned b0 = M[4*w+0], b1 = M[4*w+1], b2 = M[4*w+2], b3 = M[4*w+3];
        if (b0 > 1u || b1 > 1u || b2 > 1u || b3 > 1u) f32 = 1;
        if (b1 | b2 | b3) u8 = 1;
    }
    if (f32) atomicOr(&sh2[0], 1);
    if (u8)  atomicOr(&sh2[1], 1);
    __syncthreads();
    return sh2[0] ? 2 : (sh2[1] ? 0 : 1);
}

// ===================== launch 0: pass1 ======================================
__global__ void k_pass1(const float* __restrict__ T, const void* __restrict__ M)
{
    __shared__ int shdet[2];
    __shared__ float red[256];
    const int i = blockIdx.x, t = threadIdx.x;
    const int mdt = detect_mdt((const unsigned char*)M, t, shdet);
    const int c = t & 15, g = t >> 4;
    float s = 0.f;
    for (int j = g; j < LN; j += 16) {
        size_t idx = ((size_t)i*LN + j)*CC + c;
        float v = mask_at(M, idx, mdt) ? T[idx] : 0.f;
        d_Tm[idx] = tf32f(v);
        s += v;
    }
    red[t] = s; __syncthreads();
    if (t < 16) {
        float tot = 0.f;
        #pragma unroll
        for (int g2 = 0; g2 < 16; g2++) tot += red[g2*16 + t];
        d_cols[i*CC + t] = tot;
        size_t di = ((size_t)i*LN + i)*CC + t;
        d_diag[i*CC + t] = mask_at(M, di, mdt) ? T[di] : 0.f;
    }
}

// ===================== launch 1: fused prep (rowsum + ACD + weight frags) ===
__global__ void k_prep(const float* __restrict__ W1, const float* __restrict__ b1,
                       const float* __restrict__ W2)
{
    const int t = threadIdx.x;
    if (blockIdx.x >= LN) {
        int idx = (blockIdx.x - LN) * 256 + t;
        if (idx < 4*4*32*4) {
            int e = idx & 3, lane = (idx >> 2) & 31, q = (idx >> 7) & 3, k = idx >> 9;
            int s = 4*q + e, n = s >> 1, h = s & 1;
            int t4 = lane >> 2, tq = lane & 3;
            int col = k*8 + tq + 4*h;
            // PERMUTED: B-col position t4 holds channel (t4>>1) + 4*(t4&1)
            int o = n*8 + (t4 >> 1) + 4*(t4 & 1);
            float v = (col < 16) ? W1[o*240 + 7*16 + col]
                                 : W1[o*240 + 6*16 + (col - 16)];
            d_W1F[idx] = tf32f(v);
        } else if (idx < 4*4*32*4 + 8*4*32*4) {
            int qq = idx - 4*4*32*4;
            int e = qq & 3, lane = (qq >> 2) & 31, q = (qq >> 7) & 3, k = qq >> 9;
            int s = 4*q + e, n = s >> 1, h = s & 1;
            int t4 = lane >> 2, tq = lane & 3;
            int col = k*8 + tq + 4*h;
            d_W2F[qq] = tf32f(W2[(n*8 + t4)*64 + col]);
        }
        return;
    }

    const int node = blockIdx.x;
    const int o = t >> 2, part = t & 3;
    __shared__ float sd[16], sr[16], sc[16], st[16], sa[16];
    __shared__ float red[256];

    {   // rowsum for this node (column-strided over Tm)
        const int c = t & 15, g = t >> 4;
        float s = 0.f;
        for (int l = g; l < LN; l += 16)
            s += d_Tm[((size_t)l*LN + node)*CC + c];
        red[t] = s; __syncthreads();
        if (t < 16) {
            float a = 0.f;
            #pragma unroll
            for (int g2 = 0; g2 < 16; g2++) a += red[g2*16 + t];
            sr[t] = a;
        }
        __syncthreads();
    }
    {   // trace / all_sum (L2-hot)
        const int c = t & 15, g = t >> 4;
        float s1 = 0.f, s2 = 0.f;
        for (int k = g; k < LN; k += 16) {
            s1 += d_diag[k*CC + c];
            s2 += d_cols[k*CC + c];
        }
        red[t] = s1; __syncthreads();
        if (t < 16) {
            float a = 0.f;
            #pragma unroll
            for (int g2 = 0; g2 < 16; g2++) a += red[g2*16 + t];
            st[t] = a;
        }
        __syncthreads();
        red[t] = s2; __syncthreads();
        if (t < 16) {
            float a = 0.f;
            #pragma unroll
            for (int g2 = 0; g2 < 16; g2++) a += red[g2*16 + t];
            sa[t] = a;
        }
    }
    if (t < 16) {
        sd[t] = d_diag[node*CC + t];
        sc[t] = d_cols[node*CC + t];
    }
    __syncthreads();

    const float* w = W1 + o*240;
    float A = 0.f, CB = 0.f, D = 0.f;
    const int c0 = part * 4;
    #pragma unroll
    for (int e = 0; e < 4; e++) {
        int c = c0 + e;
        A  = fmaf(w[ 1*16 + c], sd[c], A);
        A  = fmaf(w[ 9*16 + c], sr[c], A);
        A  = fmaf(w[10*16 + c], sc[c], A);
        CB = fmaf(w[ 8*16 + c], st[c], CB);
        CB = fmaf(w[14*16 + c], sa[c], CB);
        CB = fmaf(w[ 2*16 + c], sd[c], CB);
        CB = fmaf(w[12*16 + c], sc[c], CB);
        CB = fmaf(w[13*16 + c], sr[c], CB);
        D  = fmaf(w[ 0*16 + c], sd[c], D);
        D  = fmaf(w[ 3*16 + c], sr[c], D);
        D  = fmaf(w[ 4*16 + c], sc[c], D);
        D  = fmaf(w[ 5*16 + c], st[c], D);
        D  = fmaf(w[11*16 + c], sa[c], D);
    }
    A  += __shfl_xor_sync(0xffffffffu, A, 1);
    A  += __shfl_xor_sync(0xffffffffu, A, 2);
    CB += __shfl_xor_sync(0xffffffffu, CB, 1);
    CB += __shfl_xor_sync(0xffffffffu, CB, 2);
    D  += __shfl_xor_sync(0xffffffffu, D, 1);
    D  += __shfl_xor_sync(0xffffffffu, D, 2);
    if (part == 0) {
        // channel o lives at acc position (n = o>>3, tq = o&3, e = (o>>2)&1)
        int strip = node >> 7, wd = (node >> 5) & 3;
        int m = (node >> 4) & 1, h = (node >> 3) & 1, t4r = node & 7;
        int n = o >> 3, e = (o >> 2) & 1, tqr = o & 3;
        int fi = (((((strip*4 + wd)*2 + m)*2 + h)*8 + n)*32) + t4r*4 + tqr;
        reinterpret_cast<float*>(d_AF2)[fi*2 + e] = A;
        float CBb = CB + b1[o];
        int pos = (o & ~7) + 2*(o & 3) + ((o >> 2) & 1);
        d_CB[node*NO + pos]  = CBb;
        d_diagU[node*NO + o] = A + CBb + D;   // true-channel order
    }
}

// ===================== launch 2: main mma kernel (no diag handling) =========
__global__ __launch_bounds__(128, 3)
void k_main_mma(const float* __restrict__ b2, float* __restrict__ out)
{
    __shared__ float buf[128 * PAD];

    const int tid = threadIdx.x;
    const int wid = tid >> 5, lane = tid & 31;
    const int t4 = lane >> 2, tq = lane & 3;
    const int i  = blockIdx.y;
    const int j0 = blockIdx.x * 128;

    // ---- X build (32 cols: Tm(i,j,:) | Tm(j,i,:)) ----
    const float4* TmV = reinterpret_cast<const float4*>(d_Tm) + ((size_t)i*LN + j0)*4;
    #pragma unroll
    for (int s = 0; s < 4; s++) {
        int idx = s*128 + tid;
        int r = idx >> 2, q = idx & 3;
        *reinterpret_cast<float4*>(&buf[r*PAD + q*4]) = TmV[r*4 + q];
    }
    #pragma unroll
    for (int s = 0; s < 4; s++) {
        int r = s*32 + (tid >> 2), q = tid & 3;
        float4 v = *reinterpret_cast<const float4*>(
            d_Tm + ((size_t)(j0 + r)*LN + i)*CC + q*4);
        *reinterpret_cast<float4*>(&buf[r*PAD + 16 + q*4]) = v;
    }
    __syncthreads();

    const int lm_g = lane >> 3, lm_r = lane & 7;
    const uint32_t lm_base = smem_u32(buf) +
        (uint32_t)(((wid*32 + (lm_g & 1)*8 + lm_r)*PAD + (lm_g >> 1)*4) * 4);

    // ---- GEMM1: u[32x64] = X[32x32] @ W1F^T (4 k-tiles, permuted cols) ----
    float u[2][8][4];
    #pragma unroll
    for (int m = 0; m < 2; m++)
        #pragma unroll
        for (int n = 0; n < 8; n++)
            #pragma unroll
            for (int c = 0; c < 4; c++) u[m][n][c] = 0.f;

    #pragma unroll
    for (int k = 0; k < 4; k++) {
        uint32_t a[2][4];
        ldsm4(a[0], lm_base + (uint32_t)((0*16*PAD + k*8) * 4));
        ldsm4(a[1], lm_base + (uint32_t)((1*16*PAD + k*8) * 4));
        float4 bq[4];
        const float4* wp = reinterpret_cast<const float4*>(d_W1F) + (k*4)*32 + lane;
        bq[0] = wp[0]; bq[1] = wp[32]; bq[2] = wp[64]; bq[3] = wp[96];
        const uint32_t* bb = reinterpret_cast<const uint32_t*>(bq);
        #pragma unroll
        for (int n = 0; n < 8; n++) {
            mma8(u[0][n], a[0], bb[2*n], bb[2*n+1]);
            mma8(u[1][n], a[1], bb[2*n], bb[2*n+1]);
        }
    }

    // ---- epilogue 1 (registers): + A + CB[i], relu, tf32 -----------------
    float2 cb[8];
    #pragma unroll
    for (int n = 0; n < 8; n++)
        cb[n] = *reinterpret_cast<const float2*>(d_CB + i*NO + n*8 + 2*tq);

    const float2* afBase = d_AF2 + ((size_t)blockIdx.x*4 + wid)*2*2*8*32;

    #pragma unroll
    for (int m = 0; m < 2; m++) {
        const float2* af0 = afBase + (m*2 + 0)*8*32;
        const float2* af1 = afBase + (m*2 + 1)*8*32;
        #pragma unroll
        for (int n = 0; n < 8; n++) {
            float2 A1 = af0[n*32 + lane];
            float2 A2 = af1[n*32 + lane];
            u[m][n][0] = tf32f(fmaxf(u[m][n][0] + A1.x + cb[n].x, 0.f));
            u[m][n][1] = tf32f(fmaxf(u[m][n][1] + A1.y + cb[n].y, 0.f));
            u[m][n][2] = tf32f(fmaxf(u[m][n][2] + A2.x + cb[n].x, 0.f));
            u[m][n][3] = tf32f(fmaxf(u[m][n][3] + A2.y + cb[n].y, 0.f));
        }
    }

    // ---- GEMM2: A-fragments straight from u ------------------------------
    float o2[2][8][4];
    #pragma unroll
    for (int m = 0; m < 2; m++)
        #pragma unroll
        for (int n = 0; n < 8; n++)
            #pragma unroll
            for (int c = 0; c < 4; c++) o2[m][n][c] = 0.f;

    #pragma unroll
    for (int k = 0; k < 8; k++) {
        float4 bq[4];
        const float4* wp = reinterpret_cast<const float4*>(d_W2F) + (k*4)*32 + lane;
        bq[0] = wp[0]; bq[1] = wp[32]; bq[2] = wp[64]; bq[3] = wp[96];
        const uint32_t* bb = reinterpret_cast<const uint32_t*>(bq);
        #pragma unroll
        for (int m = 0; m < 2; m++) {
            uint32_t a[4];
            a[0] = __float_as_uint(u[m][k][0]);   // (t4,    col tq)
            a[1] = __float_as_uint(u[m][k][2]);   // (t4+8,  col tq)
            a[2] = __float_as_uint(u[m][k][1]);   // (t4,    col tq+4)
            a[3] = __float_as_uint(u[m][k][3]);   // (t4+8,  col tq+4)
            #pragma unroll
            for (int n = 0; n < 8; n++)
                mma8(o2[m][n], a, bb[2*n], bb[2*n+1]);
        }
    }

    // ---- epilogue 2: + b2, plain v2 stores (let L2 coalesce sectors) -----
    float2 b2v[8];
    #pragma unroll
    for (int n = 0; n < 8; n++)
        b2v[n] = *reinterpret_cast<const float2*>(b2 + n*8 + 2*tq);

    #pragma unroll
    for (int m = 0; m < 2; m++) {
        const int r1 = wid*32 + m*16 + t4;
        const int j1 = j0 + r1, j2 = j1 + 8;
        float* o1 = out + ((size_t)i*LN + j1)*NO;
        float* o8 = out + ((size_t)i*LN + j2)*NO;
        #pragma unroll
        for (int n = 0; n < 8; n++) {
            const int col = n*8 + 2*tq;
            float2 s1, s2;
            s1.x = o2[m][n][0] + b2v[n].x; s1.y = o2[m][n][1] + b2v[n].y;
            s2.x = o2[m][n][2] + b2v[n].x; s2.y = o2[m][n][3] + b2v[n].y;
            *reinterpret_cast<float2*>(o1 + col) = s1;
            *reinterpret_cast<float2*>(o8 + col) = s2;
        }
    }
}

// ===================== launch 3: diagonal fixup =============================
// out[i][i][:] = W2 @ relu(Wf·Tm[i,i] dup + diagU[i]) + b2  (overwrites main)
__global__ void k_fix(const float* __restrict__ W1, const float* __restrict__ W2,
                      const float* __restrict__ b2, float* __restrict__ out)
{
    const int i = blockIdx.x, o = threadIdx.x;   // o = true channel, 64 threads
    __shared__ float x16[16], ur[64];
    if (o < 16) x16[o] = d_Tm[((size_t)i*LN + i)*CC + o];
    __syncthreads();
    float u = d_diagU[i*NO + o];
    #pragma unroll
    for (int c = 0; c < 16; c++) {
        float x = x16[c];
        u = fmaf(tf32f(W1[o*240 + 7*16 + c]), x, u);
        u = fmaf(tf32f(W1[o*240 + 6*16 + c]), x, u);
    }
    ur[o] = tf32f(fmaxf(u, 0.f));
    __syncthreads();
    float acc = b2[o];
    #pragma unroll
    for (int k = 0; k < 64; k++)
        acc = fmaf(tf32f(W2[o*64 + k]), ur[k], acc);
    out[((size_t)i*LN + i)*NO + o] = acc;
}

// ===================== launch ===============================================
extern "C" void kernel_launch(void* const* d_in, const int* in_sizes, int n_in,
                              void* d_out, int out_size)
{
    const float* T  = (const float*)d_in[0];
    const void*  M  = d_in[1];
    const float* W1 = (const float*)d_in[2];
    const float* b1 = (const float*)d_in[3];
    const float* W2 = (const float*)d_in[4];
    const float* b2 = (const float*)d_in[5];
    float*       out = (float*)d_out;

    k_pass1<<<LN, 256>>>(T, M);                            // launch 0
    k_prep<<<LN + 24, 256>>>(W1, b1, W2);                  // launch 1

    dim3 grid(LN/128, LN);
    k_main_mma<<<grid, 128>>>(b2, out);                    // launch 2
    k_fix<<<LN, 64>>>(W1, W2, b2, out);                    // launch 3
}

// round 15
// speedup vs baseline: 1.0559x; 1.0559x over previous
#include <cuda_runtime.h>
#include <cstdint>
#include <cstddef>

#define LN  1024
#define CC  16
#define NO  64
#define PAD 36      // buf row stride (X staging only): 36 mod 32 = 4, ldmatrix-clean

// ===================== scratch globals ======================================
__device__ float d_Tm[LN*LN*CC];   // masked T, tf32-rounded
__device__ float d_diag[LN*CC];
__device__ float d_cols[LN*CC];
// A-bias in mma fragment order (PERMUTED channels): [strip][warp][m][h][n][lane]
__device__ float2 d_AF2[8*4*2*2*8*32];
__device__ float d_CB[LN*NO];      // permuted channel positions
__device__ float d_diagO[LN*NO];   // FINAL diagonal outputs (true channel order)
// weight fragments, lane-coalesced: flat = ((k*4+q)*32 + lane)*4 + e
// W1F B-columns PERMUTED: position t4 holds channel (t4>>1)+4*(t4&1) within n-tile
__device__ float d_W1F[4*4*32*4];
__device__ float d_W2F[8*4*32*4];  // unpermuted

// ===================== helpers ==============================================
__device__ __forceinline__ float tf32f(float x) {
    uint32_t u;
    asm("cvt.rna.tf32.f32 %0, %1;" : "=r"(u) : "f"(x));
    return __uint_as_float(u);
}
__device__ __forceinline__ void mma8(float c[4], const uint32_t a[4],
                                     uint32_t b0, uint32_t b1) {
    asm volatile(
        "mma.sync.aligned.m16n8k8.row.col.f32.tf32.tf32.f32 "
        "{%0,%1,%2,%3}, {%4,%5,%6,%7}, {%8,%9}, {%0,%1,%2,%3};"
        : "+f"(c[0]), "+f"(c[1]), "+f"(c[2]), "+f"(c[3])
        : "r"(a[0]), "r"(a[1]), "r"(a[2]), "r"(a[3]), "r"(b0), "r"(b1));
}
__device__ __forceinline__ void ldsm4(uint32_t a[4], uint32_t addr) {
    asm volatile("ldmatrix.sync.aligned.m8n8.x4.shared.b16 {%0,%1,%2,%3}, [%4];"
                 : "=r"(a[0]), "=r"(a[1]), "=r"(a[2]), "=r"(a[3]) : "r"(addr));
}
__device__ __forceinline__ uint32_t smem_u32(const void* p) {
    return (uint32_t)__cvta_generic_to_shared(p);
}
__device__ __forceinline__ bool mask_at(const void* M, size_t idx, int mdt)
{
    if (mdt == 0) return ((const unsigned char*)M)[idx] != 0;
    if (mdt == 1) return ((const int*)M)[idx] != 0;
    return ((const float*)M)[idx] != 0.f;
}
__device__ __forceinline__ int detect_mdt(const unsigned char* __restrict__ M,
                                          int t, int* sh2)
{
    if (t == 0) { sh2[0] = 0; sh2[1] = 0; }
    __syncthreads();
    int f32 = 0, u8 = 0;
    for (int w = t; w < 1024; w += 256) {
        unsigned b0 = M[4*w+0], b1 = M[4*w+1], b2 = M[4*w+2], b3 = M[4*w+3];
        if (b0 > 1u || b1 > 1u || b2 > 1u || b3 > 1u) f32 = 1;
        if (b1 | b2 | b3) u8 = 1;
    }
    if (f32) atomicOr(&sh2[0], 1);
    if (u8)  atomicOr(&sh2[1], 1);
    __syncthreads();
    return sh2[0] ? 2 : (sh2[1] ? 0 : 1);
}

// ===================== launch 0: pass1 ======================================
__global__ void k_pass1(const float* __restrict__ T, const void* __restrict__ M)
{
    __shared__ int shdet[2];
    __shared__ float red[256];
    const int i = blockIdx.x, t = threadIdx.x;
    const int mdt = detect_mdt((const unsigned char*)M, t, shdet);
    const int c = t & 15, g = t >> 4;
    float s = 0.f;
    for (int j = g; j < LN; j += 16) {
        size_t idx = ((size_t)i*LN + j)*CC + c;
        float v = mask_at(M, idx, mdt) ? T[idx] : 0.f;
        d_Tm[idx] = tf32f(v);
        s += v;
    }
    red[t] = s; __syncthreads();
    if (t < 16) {
        float tot = 0.f;
        #pragma unroll
        for (int g2 = 0; g2 < 16; g2++) tot += red[g2*16 + t];
        d_cols[i*CC + t] = tot;
        size_t di = ((size_t)i*LN + i)*CC + t;
        d_diag[i*CC + t] = mask_at(M, di, mdt) ? T[di] : 0.f;
    }
}

// ===================== launch 1: fused prep =================================
// node blocks: rowsum + trace/all + AF2/CB + FULL diagonal output (fp32)
// tail blocks: weight fragment layouts
__global__ void k_prep(const float* __restrict__ W1, const float* __restrict__ b1,
                       const float* __restrict__ W2, const float* __restrict__ b2)
{
    const int t = threadIdx.x;
    if (blockIdx.x >= LN) {
        int idx = (blockIdx.x - LN) * 256 + t;
        if (idx < 4*4*32*4) {
            int e = idx & 3, lane = (idx >> 2) & 31, q = (idx >> 7) & 3, k = idx >> 9;
            int s = 4*q + e, n = s >> 1, h = s & 1;
            int t4 = lane >> 2, tq = lane & 3;
            int col = k*8 + tq + 4*h;
            // PERMUTED: B-col position t4 holds channel (t4>>1) + 4*(t4&1)
            int o = n*8 + (t4 >> 1) + 4*(t4 & 1);
            float v = (col < 16) ? W1[o*240 + 7*16 + col]
                                 : W1[o*240 + 6*16 + (col - 16)];
            d_W1F[idx] = tf32f(v);
        } else if (idx < 4*4*32*4 + 8*4*32*4) {
            int qq = idx - 4*4*32*4;
            int e = qq & 3, lane = (qq >> 2) & 31, q = (qq >> 7) & 3, k = qq >> 9;
            int s = 4*q + e, n = s >> 1, h = s & 1;
            int t4 = lane >> 2, tq = lane & 3;
            int col = k*8 + tq + 4*h;
            d_W2F[qq] = tf32f(W2[(n*8 + t4)*64 + col]);
        }
        return;
    }

    const int node = blockIdx.x;
    const int o = t >> 2, part = t & 3;
    __shared__ float sd[16], sr[16], sc[16], st[16], sa[16];
    __shared__ float red[256];
    __shared__ float ur[64];

    {   // rowsum for this node (column-strided over Tm)
        const int c = t & 15, g = t >> 4;
        float s = 0.f;
        for (int l = g; l < LN; l += 16)
            s += d_Tm[((size_t)l*LN + node)*CC + c];
        red[t] = s; __syncthreads();
        if (t < 16) {
            float a = 0.f;
            #pragma unroll
            for (int g2 = 0; g2 < 16; g2++) a += red[g2*16 + t];
            sr[t] = a;
        }
        __syncthreads();
    }
    {   // trace / all_sum (L2-hot)
        const int c = t & 15, g = t >> 4;
        float s1 = 0.f, s2 = 0.f;
        for (int k = g; k < LN; k += 16) {
            s1 += d_diag[k*CC + c];
            s2 += d_cols[k*CC + c];
        }
        red[t] = s1; __syncthreads();
        if (t < 16) {
            float a = 0.f;
            #pragma unroll
            for (int g2 = 0; g2 < 16; g2++) a += red[g2*16 + t];
            st[t] = a;
        }
        __syncthreads();
        red[t] = s2; __syncthreads();
        if (t < 16) {
            float a = 0.f;
            #pragma unroll
            for (int g2 = 0; g2 < 16; g2++) a += red[g2*16 + t];
            sa[t] = a;
        }
    }
    if (t < 16) {
        sd[t] = d_diag[node*CC + t];
        sc[t] = d_cols[node*CC + t];
    }
    __syncthreads();

    const float* w = W1 + o*240;
    float A = 0.f, CB = 0.f, D = 0.f, W76 = 0.f;
    const int c0 = part * 4;
    #pragma unroll
    for (int e = 0; e < 4; e++) {
        int c = c0 + e;
        A  = fmaf(w[ 1*16 + c], sd[c], A);
        A  = fmaf(w[ 9*16 + c], sr[c], A);
        A  = fmaf(w[10*16 + c], sc[c], A);
        CB = fmaf(w[ 8*16 + c], st[c], CB);
        CB = fmaf(w[14*16 + c], sa[c], CB);
        CB = fmaf(w[ 2*16 + c], sd[c], CB);
        CB = fmaf(w[12*16 + c], sc[c], CB);
        CB = fmaf(w[13*16 + c], sr[c], CB);
        D  = fmaf(w[ 0*16 + c], sd[c], D);
        D  = fmaf(w[ 3*16 + c], sr[c], D);
        D  = fmaf(w[ 4*16 + c], sc[c], D);
        D  = fmaf(w[ 5*16 + c], st[c], D);
        D  = fmaf(w[11*16 + c], sa[c], D);
        W76 = fmaf(w[ 7*16 + c], sd[c], W76);  // identity block @ Tm[i,i]
        W76 = fmaf(w[ 6*16 + c], sd[c], W76);  // transpose block @ Tm[i,i]
    }
    A   += __shfl_xor_sync(0xffffffffu, A, 1);
    A   += __shfl_xor_sync(0xffffffffu, A, 2);
    CB  += __shfl_xor_sync(0xffffffffu, CB, 1);
    CB  += __shfl_xor_sync(0xffffffffu, CB, 2);
    D   += __shfl_xor_sync(0xffffffffu, D, 1);
    D   += __shfl_xor_sync(0xffffffffu, D, 2);
    W76 += __shfl_xor_sync(0xffffffffu, W76, 1);
    W76 += __shfl_xor_sync(0xffffffffu, W76, 2);
    float CBb = CB + b1[o];
    if (part == 0) {
        // channel o lives at acc position (n = o>>3, tq = o&3, e = (o>>2)&1)
        int strip = node >> 7, wd = (node >> 5) & 3;
        int m = (node >> 4) & 1, h = (node >> 3) & 1, t4r = node & 7;
        int n = o >> 3, e = (o >> 2) & 1, tqr = o & 3;
        int fi = (((((strip*4 + wd)*2 + m)*2 + h)*8 + n)*32) + t4r*4 + tqr;
        reinterpret_cast<float*>(d_AF2)[fi*2 + e] = A;
        int pos = (o & ~7) + 2*(o & 3) + ((o >> 2) & 1);
        d_CB[node*NO + pos] = CBb;
        ur[o] = fmaxf(A + CBb + D + W76, 0.f);   // relu(u_diag), fp32
    }
    __syncthreads();

    // diagonal second layer: d_diagO[node][o] = W2[o] @ ur + b2[o]
    {
        const float* w2r = W2 + o*64 + part*16;
        float acc = 0.f;
        #pragma unroll
        for (int k = 0; k < 16; k++)
            acc = fmaf(w2r[k], ur[part*16 + k], acc);
        acc += __shfl_xor_sync(0xffffffffu, acc, 1);
        acc += __shfl_xor_sync(0xffffffffu, acc, 2);
        if (part == 0)
            d_diagO[node*NO + o] = acc + b2[o];
    }
}

// ===================== launch 2: main mma kernel (no diag handling) =========
__global__ __launch_bounds__(128, 3)
void k_main_mma(const float* __restrict__ b2, float* __restrict__ out)
{
    __shared__ float buf[128 * PAD];

    const int tid = threadIdx.x;
    const int wid = tid >> 5, lane = tid & 31;
    const int t4 = lane >> 2, tq = lane & 3;
    const int i  = blockIdx.y;
    const int j0 = blockIdx.x * 128;

    // ---- X build (32 cols: Tm(i,j,:) | Tm(j,i,:)) ----
    const float4* TmV = reinterpret_cast<const float4*>(d_Tm) + ((size_t)i*LN + j0)*4;
    #pragma unroll
    for (int s = 0; s < 4; s++) {
        int idx = s*128 + tid;
        int r = idx >> 2, q = idx & 3;
        *reinterpret_cast<float4*>(&buf[r*PAD + q*4]) = TmV[r*4 + q];
    }
    #pragma unroll
    for (int s = 0; s < 4; s++) {
        int r = s*32 + (tid >> 2), q = tid & 3;
        float4 v = *reinterpret_cast<const float4*>(
            d_Tm + ((size_t)(j0 + r)*LN + i)*CC + q*4);
        *reinterpret_cast<float4*>(&buf[r*PAD + 16 + q*4]) = v;
    }
    __syncthreads();

    const int lm_g = lane >> 3, lm_r = lane & 7;
    const uint32_t lm_base = smem_u32(buf) +
        (uint32_t)(((wid*32 + (lm_g & 1)*8 + lm_r)*PAD + (lm_g >> 1)*4) * 4);

    // ---- GEMM1: u[32x64] = X[32x32] @ W1F^T (4 k-tiles, permuted cols) ----
    float u[2][8][4];
    #pragma unroll
    for (int m = 0; m < 2; m++)
        #pragma unroll
        for (int n = 0; n < 8; n++)
            #pragma unroll
            for (int c = 0; c < 4; c++) u[m][n][c] = 0.f;

    #pragma unroll
    for (int k = 0; k < 4; k++) {
        uint32_t a[2][4];
        ldsm4(a[0], lm_base + (uint32_t)((0*16*PAD + k*8) * 4));
        ldsm4(a[1], lm_base + (uint32_t)((1*16*PAD + k*8) * 4));
        float4 bq[4];
        const float4* wp = reinterpret_cast<const float4*>(d_W1F) + (k*4)*32 + lane;
        bq[0] = wp[0]; bq[1] = wp[32]; bq[2] = wp[64]; bq[3] = wp[96];
        const uint32_t* bb = reinterpret_cast<const uint32_t*>(bq);
        #pragma unroll
        for (int n = 0; n < 8; n++) {
            mma8(u[0][n], a[0], bb[2*n], bb[2*n+1]);
            mma8(u[1][n], a[1], bb[2*n], bb[2*n+1]);
        }
    }

    // ---- epilogue 1 (registers): + A + CB[i], relu, tf32 -----------------
    float2 cb[8];
    #pragma unroll
    for (int n = 0; n < 8; n++)
        cb[n] = *reinterpret_cast<const float2*>(d_CB + i*NO + n*8 + 2*tq);

    const float2* afBase = d_AF2 + ((size_t)blockIdx.x*4 + wid)*2*2*8*32;

    #pragma unroll
    for (int m = 0; m < 2; m++) {
        const float2* af0 = afBase + (m*2 + 0)*8*32;
        const float2* af1 = afBase + (m*2 + 1)*8*32;
        #pragma unroll
        for (int n = 0; n < 8; n++) {
            float2 A1 = af0[n*32 + lane];
            float2 A2 = af1[n*32 + lane];
            u[m][n][0] = tf32f(fmaxf(u[m][n][0] + A1.x + cb[n].x, 0.f));
            u[m][n][1] = tf32f(fmaxf(u[m][n][1] + A1.y + cb[n].y, 0.f));
            u[m][n][2] = tf32f(fmaxf(u[m][n][2] + A2.x + cb[n].x, 0.f));
            u[m][n][3] = tf32f(fmaxf(u[m][n][3] + A2.y + cb[n].y, 0.f));
        }
    }

    // ---- GEMM2: A-fragments straight from u ------------------------------
    float o2[2][8][4];
    #pragma unroll
    for (int m = 0; m < 2; m++)
        #pragma unroll
        for (int n = 0; n < 8; n++)
            #pragma unroll
            for (int c = 0; c < 4; c++) o2[m][n][c] = 0.f;

    #pragma unroll
    for (int k = 0; k < 8; k++) {
        float4 bq[4];
        const float4* wp = reinterpret_cast<const float4*>(d_W2F) + (k*4)*32 + lane;
        bq[0] = wp[0]; bq[1] = wp[32]; bq[2] = wp[64]; bq[3] = wp[96];
        const uint32_t* bb = reinterpret_cast<const uint32_t*>(bq);
        #pragma unroll
        for (int m = 0; m < 2; m++) {
            uint32_t a[4];
            a[0] = __float_as_uint(u[m][k][0]);   // (t4,    col tq)
            a[1] = __float_as_uint(u[m][k][2]);   // (t4+8,  col tq)
            a[2] = __float_as_uint(u[m][k][1]);   // (t4,    col tq+4)
            a[3] = __float_as_uint(u[m][k][3]);   // (t4+8,  col tq+4)
            #pragma unroll
            for (int n = 0; n < 8; n++)
                mma8(o2[m][n], a, bb[2*n], bb[2*n+1]);
        }
    }

    // ---- epilogue 2: + b2, plain v2 stores -------------------------------
    float2 b2v[8];
    #pragma unroll
    for (int n = 0; n < 8; n++)
        b2v[n] = *reinterpret_cast<const float2*>(b2 + n*8 + 2*tq);

    #pragma unroll
    for (int m = 0; m < 2; m++) {
        const int r1 = wid*32 + m*16 + t4;
        const int j1 = j0 + r1, j2 = j1 + 8;
        float* o1 = out + ((size_t)i*LN + j1)*NO;
        float* o8 = out + ((size_t)i*LN + j2)*NO;
        #pragma unroll
        for (int n = 0; n < 8; n++) {
            const int col = n*8 + 2*tq;
            float2 s1, s2;
            s1.x = o2[m][n][0] + b2v[n].x; s1.y = o2[m][n][1] + b2v[n].y;
            s2.x = o2[m][n][2] + b2v[n].x; s2.y = o2[m][n][3] + b2v[n].y;
            *reinterpret_cast<float2*>(o1 + col) = s1;
            *reinterpret_cast<float2*>(o8 + col) = s2;
        }
    }
}

// ===================== launch 3: diagonal copy (trivial) ====================
__global__ void k_fix(float* __restrict__ out)
{
    int idx = blockIdx.x * 256 + threadIdx.x;   // 65536 total
    int i = idx >> 6, o = idx & 63;
    out[((size_t)i*LN + i)*NO + o] = d_diagO[idx];
}

// ===================== launch ===============================================
extern "C" void kernel_launch(void* const* d_in, const int* in_sizes, int n_in,
                              void* d_out, int out_size)
{
    const float* T  = (const float*)d_in[0];
    const void*  M  = d_in[1];
    const float* W1 = (const float*)d_in[2];
    const float* b1 = (const float*)d_in[3];
    const float* W2 = (const float*)d_in[4];
    const float* b2 = (const float*)d_in[5];
    float*       out = (float*)d_out;

    k_pass1<<<LN, 256>>>(T, M);                            // launch 0
    k_prep<<<LN + 24, 256>>>(W1, b1, W2, b2);              // launch 1

    dim3 grid(LN/128, LN);
    k_main_mma<<<grid, 128>>>(b2, out);                    // launch 2
    k_fix<<<256, 256>>>(out);                              // launch 3
}